// round 1
// baseline (speedup 1.0000x reference)
#include <cuda_runtime.h>
#include <math.h>

#define B     64
#define T     512
#define NSTEP 128
#define S     512
#define H2D   512
#define ATT   128
#define NCLS  64

// ---------------- scratch (static device globals; no allocation) ----------------
__device__ float g_psi[B * T * ATT];       // 16.8 MB  psi_h = h @ Wpsi.T + bpsi
__device__ float g_h1[2][B * S];
__device__ float g_h2[2][B * S];
__device__ float g_c1[B * S];
__device__ float g_c2[B * S];
__device__ float g_ctx[B * H2D];

__device__ __forceinline__ float sigf(float v) { return 1.0f / (1.0f + expf(-v)); }

// ---------------- init: states + initial context = h[:,0,:] ----------------
__global__ void k_init(const float* __restrict__ h)
{
    int b = blockIdx.x;
    for (int d = threadIdx.x; d < S; d += blockDim.x) {
        g_ctx[b * S + d]   = h[(size_t)b * T * H2D + d];
        g_h1[0][b * S + d] = 0.f;
        g_h1[1][b * S + d] = 0.f;
        g_h2[0][b * S + d] = 0.f;
        g_h2[1][b * S + d] = 0.f;
        g_c1[b * S + d]    = 0.f;
        g_c2[b * S + d]    = 0.f;
    }
}

// ---------------- psi_h precompute: GEMM per batch, tile 32t x 128a ----------------
__global__ void k_psi(const float* __restrict__ h,
                      const float* __restrict__ Wpsi,
                      const float* __restrict__ bpsi)
{
    __shared__ __align__(16) float hs[32][36];
    __shared__ __align__(16) float ws[128][36];
    int b   = blockIdx.y;
    int t0  = blockIdx.x * 32;
    int tid = threadIdx.x;
    int tg  = tid & 7;    // t rows tg*4 .. +4
    int ag  = tid >> 3;   // a cols ag*4 .. +4

    float acc[16];
#pragma unroll
    for (int i = 0; i < 16; ++i) acc[i] = 0.f;

    for (int dc = 0; dc < H2D; dc += 32) {
#pragma unroll
        for (int i = 0; i < 4; ++i) {
            int lin = tid + i * 256;
            int r = lin >> 5, c = lin & 31;
            hs[r][c] = h[((size_t)b * T + t0 + r) * H2D + dc + c];
        }
#pragma unroll
        for (int i = 0; i < 16; ++i) {
            int lin = tid + i * 256;
            int r = lin >> 5, c = lin & 31;
            ws[r][c] = Wpsi[r * H2D + dc + c];
        }
        __syncthreads();
#pragma unroll
        for (int k = 0; k < 32; k += 4) {
            float4 hv[4], wv[4];
#pragma unroll
            for (int j = 0; j < 4; ++j) hv[j] = *(const float4*)&hs[tg * 4 + j][k];
#pragma unroll
            for (int j = 0; j < 4; ++j) wv[j] = *(const float4*)&ws[ag * 4 + j][k];
#pragma unroll
            for (int i = 0; i < 4; ++i)
#pragma unroll
                for (int j = 0; j < 4; ++j) {
                    acc[i * 4 + j] = fmaf(hv[i].x, wv[j].x, acc[i * 4 + j]);
                    acc[i * 4 + j] = fmaf(hv[i].y, wv[j].y, acc[i * 4 + j]);
                    acc[i * 4 + j] = fmaf(hv[i].z, wv[j].z, acc[i * 4 + j]);
                    acc[i * 4 + j] = fmaf(hv[i].w, wv[j].w, acc[i * 4 + j]);
                }
        }
        __syncthreads();
    }
#pragma unroll
    for (int i = 0; i < 4; ++i)
#pragma unroll
        for (int j = 0; j < 4; ++j) {
            int tt = t0 + tg * 4 + i;
            int a  = ag * 4 + j;
            g_psi[((size_t)b * T + tt) * ATT + a] = acc[i * 4 + j] + bpsi[a];
        }
}

// ---------------- fused LSTM cell GEMM + gate nonlinearity ----------------
// which==0: gates = Wih0[:,64:] @ ctx + Whh0 @ h1_prev  (+ onehot column pick)
// which==1: gates = Wih1 @ h1_new + Whh1 @ h2_prev
// Block owns 4 hidden units (16 gate rows) x all 64 batches. K = 1024.
__global__ void k_lstm(const float* __restrict__ Wih, int pitchIh, int colOff,
                       const float* __restrict__ Whh,
                       const float* __restrict__ bih, const float* __restrict__ bhh,
                       const int* __restrict__ x, int t, int which, int par)
{
    __shared__ __align__(16) float As[16][36];
    __shared__ __align__(16) float Bs[64][36];

    const float* zA;
    const float* zB;
    float* hout;
    float* cst;
    if (which == 0) {
        zA = g_ctx;        zB = g_h1[par];
        hout = g_h1[par ^ 1]; cst = g_c1;
    } else {
        zA = g_h1[par ^ 1]; zB = g_h2[par];
        hout = g_h2[par ^ 1]; cst = g_c2;
    }

    int tid = threadIdx.x;
    int ub  = blockIdx.x * 4;   // first unit of this block
    int mg  = tid & 3;          // local unit
    int n   = tid >> 2;         // batch

    // A loader: 16 rows x 32 k, 2 elems per thread
    int l0 = tid, l1 = tid + 256;
    int ri0 = l0 >> 5, kk0 = l0 & 31;
    int ri1 = l1 >> 5, kk1 = l1 & 31;
    int grow0 = (ri0 & 3) * 512 + ub + (ri0 >> 2);
    int grow1 = (ri1 & 3) * 512 + ub + (ri1 >> 2);
    // B loader: 64 batches x 32 k, 8 elems per thread
    int bn = tid >> 2;
    int bk = (tid & 3) * 8;

    float a0, a1;
    float4 b0, b1;
    {   // prologue: tile 0 (k in [0,32) -> always zA / Wih part)
        b0 = *(const float4*)&zA[bn * 512 + bk];
        b1 = *(const float4*)&zA[bn * 512 + bk + 4];
        a0 = Wih[grow0 * pitchIh + colOff + kk0];
        a1 = Wih[grow1 * pitchIh + colOff + kk1];
    }

    float acc0 = 0.f, acc1 = 0.f, acc2 = 0.f, acc3 = 0.f;

    for (int kt = 0; kt < 32; ++kt) {
        As[ri0][kk0] = a0;
        As[ri1][kk1] = a1;
        *(float4*)&Bs[bn][bk]     = b0;
        *(float4*)&Bs[bn][bk + 4] = b1;
        __syncthreads();

        if (kt + 1 < 32) {   // prefetch next tile during compute
            int kb = (kt + 1) * 32;
            const float* src = (kb < 512) ? zA : zB;
            int koff = kb & 511;
            b0 = *(const float4*)&src[bn * 512 + koff + bk];
            b1 = *(const float4*)&src[bn * 512 + koff + bk + 4];
            int k0 = kb + kk0;
            a0 = (k0 < 512) ? Wih[grow0 * pitchIh + colOff + k0]
                            : Whh[grow0 * 512 + (k0 - 512)];
            int k1 = kb + kk1;
            a1 = (k1 < 512) ? Wih[grow1 * pitchIh + colOff + k1]
                            : Whh[grow1 * 512 + (k1 - 512)];
        }

#pragma unroll
        for (int k = 0; k < 32; k += 4) {
            float4 bv = *(const float4*)&Bs[n][k];
            float4 av;
            av = *(const float4*)&As[mg * 4 + 0][k];
            acc0 = fmaf(av.x, bv.x, acc0); acc0 = fmaf(av.y, bv.y, acc0);
            acc0 = fmaf(av.z, bv.z, acc0); acc0 = fmaf(av.w, bv.w, acc0);
            av = *(const float4*)&As[mg * 4 + 1][k];
            acc1 = fmaf(av.x, bv.x, acc1); acc1 = fmaf(av.y, bv.y, acc1);
            acc1 = fmaf(av.z, bv.z, acc1); acc1 = fmaf(av.w, bv.w, acc1);
            av = *(const float4*)&As[mg * 4 + 2][k];
            acc2 = fmaf(av.x, bv.x, acc2); acc2 = fmaf(av.y, bv.y, acc2);
            acc2 = fmaf(av.z, bv.z, acc2); acc2 = fmaf(av.w, bv.w, acc2);
            av = *(const float4*)&As[mg * 4 + 3][k];
            acc3 = fmaf(av.x, bv.x, acc3); acc3 = fmaf(av.y, bv.y, acc3);
            acc3 = fmaf(av.z, bv.z, acc3); acc3 = fmaf(av.w, bv.w, acc3);
        }
        __syncthreads();
    }

    // epilogue: bias (+ one-hot column), gate nonlinearity, state update
    int unit = ub + mg;
    float pre[4] = {acc0, acc1, acc2, acc3};
    int cls = (which == 0) ? x[n * NSTEP + t] : 0;
#pragma unroll
    for (int g = 0; g < 4; ++g) {
        int grow = g * 512 + unit;
        pre[g] += bih[grow] + bhh[grow];
        if (which == 0) pre[g] += Wih[grow * pitchIh + cls];
    }
    float co = cst[n * S + unit];
    float cn = sigf(pre[1]) * co + sigf(pre[0]) * tanhf(pre[2]);
    float hn = sigf(pre[3]) * tanhf(cn);
    cst[n * S + unit]  = cn;
    hout[n * S + unit] = hn;
}

// ---------------- attention + output projection (one block per batch) ----------------
__global__ void k_attn(const float* __restrict__ h,
                       const float* __restrict__ Wphi, const float* __restrict__ bphi,
                       const float* __restrict__ Wcd,  const float* __restrict__ bcd,
                       float* __restrict__ out, int t, int par)
{
    __shared__ __align__(16) float h2s[S];
    __shared__ __align__(16) float phis[ATT];
    __shared__ __align__(16) float es[T];
    __shared__ __align__(16) float ctxs[H2D];
    __shared__ float red[8];

    int b    = blockIdx.x;
    int tid  = threadIdx.x;
    int wid  = tid >> 5;
    int lane = tid & 31;
    const float* h2 = g_h2[par ^ 1];

    for (int d = tid; d < S; d += 256) h2s[d] = h2[b * S + d];
    __syncthreads();

    // phi_s = Wphi @ h2 + bphi : 8 warps x 16 outputs (warp dot over 512)
    for (int a = wid * 16; a < wid * 16 + 16; ++a) {
        const float* wr = Wphi + a * S;
        float s = 0.f;
#pragma unroll 4
        for (int i = lane; i < S; i += 32) s = fmaf(wr[i], h2s[i], s);
#pragma unroll
        for (int o = 16; o > 0; o >>= 1) s += __shfl_xor_sync(0xffffffffu, s, o);
        if (lane == 0) phis[a] = s + bphi[a];
    }
    __syncthreads();

    // e[t'] = phi . psi[b,t',:] : 8 warps x 64 rows, lane holds 4 attn dims
    float ph0, ph1, ph2, ph3;
    {
        float4 p4 = *(const float4*)&phis[lane * 4];
        ph0 = p4.x; ph1 = p4.y; ph2 = p4.z; ph3 = p4.w;
    }
    const float* psib = g_psi + (size_t)b * T * ATT;
    for (int tt = wid * 64; tt < wid * 64 + 64; ++tt) {
        float4 v = *(const float4*)&psib[tt * ATT + lane * 4];
        float s = ph0 * v.x + ph1 * v.y + ph2 * v.z + ph3 * v.w;
#pragma unroll
        for (int o = 16; o > 0; o >>= 1) s += __shfl_xor_sync(0xffffffffu, s, o);
        if (lane == 0) es[tt] = s;
    }
    __syncthreads();

    // softmax over 512 (block reduce max, exp, sum, normalize)
    float m = fmaxf(es[tid], es[tid + 256]);
#pragma unroll
    for (int o = 16; o > 0; o >>= 1) m = fmaxf(m, __shfl_xor_sync(0xffffffffu, m, o));
    if (lane == 0) red[wid] = m;
    __syncthreads();
    if (tid == 0) {
        float mm = red[0];
        for (int i = 1; i < 8; ++i) mm = fmaxf(mm, red[i]);
        red[0] = mm;
    }
    __syncthreads();
    m = red[0];
    float e0 = expf(es[tid] - m), e1 = expf(es[tid + 256] - m);
    float ssum = e0 + e1;
#pragma unroll
    for (int o = 16; o > 0; o >>= 1) ssum += __shfl_xor_sync(0xffffffffu, ssum, o);
    __syncthreads();
    if (lane == 0) red[wid] = ssum;
    __syncthreads();
    if (tid == 0) {
        float s = 0.f;
        for (int i = 0; i < 8; ++i) s += red[i];
        red[0] = 1.f / s;
    }
    __syncthreads();
    float inv = red[0];
    es[tid]       = e0 * inv;
    es[tid + 256] = e1 * inv;
    __syncthreads();

    // ctx[d] = sum_t alpha[t] * h[b,t,d] : thread owns 2 dims
    {
        const float* hb = h + (size_t)b * T * H2D;
        int d = tid * 2;
        float ax = 0.f, ay = 0.f;
#pragma unroll 8
        for (int tt = 0; tt < T; ++tt) {
            float a = es[tt];
            float2 hv = *(const float2*)&hb[tt * H2D + d];
            ax = fmaf(a, hv.x, ax);
            ay = fmaf(a, hv.y, ay);
        }
        ctxs[d] = ax; ctxs[d + 1] = ay;
        g_ctx[b * H2D + d] = ax;
        g_ctx[b * H2D + d + 1] = ay;
    }
    __syncthreads();

    // p = Wcd @ [h2; ctx] + bcd : 8 warps x 8 outputs (warp dot over 1024)
    for (int c = wid * 8; c < wid * 8 + 8; ++c) {
        const float* wr = Wcd + c * (S + H2D);
        float s = 0.f;
#pragma unroll 4
        for (int i = lane; i < S; i += 32)   s = fmaf(wr[i],     h2s[i],  s);
#pragma unroll 4
        for (int i = lane; i < H2D; i += 32) s = fmaf(wr[S + i], ctxs[i], s);
#pragma unroll
        for (int o = 16; o > 0; o >>= 1) s += __shfl_xor_sync(0xffffffffu, s, o);
        if (lane == 0) out[((size_t)b * NSTEP + t) * NCLS + c] = s + bcd[c];
    }
}

// ---------------- launcher ----------------
extern "C" void kernel_launch(void* const* d_in, const int* in_sizes, int n_in,
                              void* d_out, int out_size)
{
    const int*   x    = (const int*)d_in[0];
    const float* h    = (const float*)d_in[1];
    const float* Wih0 = (const float*)d_in[2];
    const float* Whh0 = (const float*)d_in[3];
    const float* bih0 = (const float*)d_in[4];
    const float* bhh0 = (const float*)d_in[5];
    const float* Wih1 = (const float*)d_in[6];
    const float* Whh1 = (const float*)d_in[7];
    const float* bih1 = (const float*)d_in[8];
    const float* bhh1 = (const float*)d_in[9];
    const float* Wphi = (const float*)d_in[10];
    const float* bphi = (const float*)d_in[11];
    const float* Wpsi = (const float*)d_in[12];
    const float* bpsi = (const float*)d_in[13];
    const float* Wcd  = (const float*)d_in[14];
    const float* bcd  = (const float*)d_in[15];
    float* out = (float*)d_out;

    k_init<<<B, 512>>>(h);
    k_psi<<<dim3(T / 32, B), 256>>>(h, Wpsi, bpsi);

    int par = 0;
    for (int t = 0; t < NSTEP; ++t) {
        k_lstm<<<S / 4, 256>>>(Wih0, 576, 64, Whh0, bih0, bhh0, x, t, 0, par);
        k_lstm<<<S / 4, 256>>>(Wih1, 512, 0,  Whh1, bih1, bhh1, x, t, 1, par);
        k_attn<<<B, 256>>>(h, Wphi, bphi, Wcd, bcd, out, t, par);
        par ^= 1;
    }
}

// round 3
// speedup vs baseline: 1.6366x; 1.6366x over previous
#include <cuda_runtime.h>
#include <math.h>

#define B     64
#define T     512
#define NSTEP 128
#define S     512
#define H2D   512
#define ATT   128
#define NCLS  64

// ---------------- scratch (static device globals; no allocation) ----------------
__device__ float g_psi[B * T * ATT];        // psi_h = h @ Wpsi.T + bpsi
__device__ float g_alpha[B * T];            // per-step attention weights
__device__ float g_part[4 * 2048 * B];      // K-split partial gate sums
__device__ float g_h1[2][B * S];
__device__ float g_h2[2][B * S];
__device__ float g_c1[B * S];
__device__ float g_c2[B * S];
__device__ float g_ctx[B * H2D];
__device__ int   g_cntL[128];               // lstm ksplit arrival counters (which*64+grp)
__device__ int   g_cntC[64];                // ctx chunk arrival counters (per batch)

__device__ __forceinline__ float sigf(float v) { return 1.0f / (1.0f + expf(-v)); }

__device__ __forceinline__ void cp4(void* s, const void* g)
{
    unsigned sa = (unsigned)__cvta_generic_to_shared(s);
    asm volatile("cp.async.ca.shared.global [%0], [%1], 4;\n" :: "r"(sa), "l"(g));
}

// ---------------- init: states + initial context = h[:,0,:] ----------------
__global__ void k_init(const float* __restrict__ h)
{
    int b = blockIdx.x;
    for (int d = threadIdx.x; d < S; d += blockDim.x) {
        g_ctx[b * S + d]   = h[(size_t)b * T * H2D + d];
        g_h1[0][b * S + d] = 0.f;
        g_h1[1][b * S + d] = 0.f;
        g_h2[0][b * S + d] = 0.f;
        g_h2[1][b * S + d] = 0.f;
        g_c1[b * S + d]    = 0.f;
        g_c2[b * S + d]    = 0.f;
    }
    if (blockIdx.x == 0) {
        for (int i = threadIdx.x; i < 128; i += blockDim.x) g_cntL[i] = 0;
        for (int i = threadIdx.x; i < 64;  i += blockDim.x) g_cntC[i] = 0;
    }
}

// ---------------- psi_h precompute: GEMM per batch, tile 32t x 128a ----------------
__global__ void k_psi(const float* __restrict__ h,
                      const float* __restrict__ Wpsi,
                      const float* __restrict__ bpsi)
{
    __shared__ __align__(16) float hs[32][36];
    __shared__ __align__(16) float ws[128][36];
    int b   = blockIdx.y;
    int t0  = blockIdx.x * 32;
    int tid = threadIdx.x;
    int tg  = tid & 7;
    int ag  = tid >> 3;

    float acc[16];
#pragma unroll
    for (int i = 0; i < 16; ++i) acc[i] = 0.f;

    for (int dc = 0; dc < H2D; dc += 32) {
#pragma unroll
        for (int i = 0; i < 4; ++i) {
            int lin = tid + i * 256;
            int r = lin >> 5, c = lin & 31;
            hs[r][c] = h[((size_t)b * T + t0 + r) * H2D + dc + c];
        }
#pragma unroll
        for (int i = 0; i < 16; ++i) {
            int lin = tid + i * 256;
            int r = lin >> 5, c = lin & 31;
            ws[r][c] = Wpsi[r * H2D + dc + c];
        }
        __syncthreads();
#pragma unroll
        for (int k = 0; k < 32; k += 4) {
            float4 hv[4], wv[4];
#pragma unroll
            for (int j = 0; j < 4; ++j) hv[j] = *(const float4*)&hs[tg * 4 + j][k];
#pragma unroll
            for (int j = 0; j < 4; ++j) wv[j] = *(const float4*)&ws[ag * 4 + j][k];
#pragma unroll
            for (int i = 0; i < 4; ++i)
#pragma unroll
                for (int j = 0; j < 4; ++j) {
                    acc[i * 4 + j] = fmaf(hv[i].x, wv[j].x, acc[i * 4 + j]);
                    acc[i * 4 + j] = fmaf(hv[i].y, wv[j].y, acc[i * 4 + j]);
                    acc[i * 4 + j] = fmaf(hv[i].z, wv[j].z, acc[i * 4 + j]);
                    acc[i * 4 + j] = fmaf(hv[i].w, wv[j].w, acc[i * 4 + j]);
                }
        }
        __syncthreads();
    }
#pragma unroll
    for (int i = 0; i < 4; ++i)
#pragma unroll
        for (int j = 0; j < 4; ++j) {
            int tt = t0 + tg * 4 + i;
            int a  = ag * 4 + j;
            g_psi[((size_t)b * T + tt) * ATT + a] = acc[i * 4 + j] + bpsi[a];
        }
}

// ---------------- LSTM: K-split-4 GEMM + fused gate epilogue (last block) --------
// grid 256 = 64 unit-groups (8 units = 32 gate rows) x 4 K-splits of 256.
// block 128 threads; thread tile 4 rows x 4 batches; cp.async 2-stage pipeline.
__global__ void __launch_bounds__(128) k_lstm(
        const float* __restrict__ Wih, int pIh, int colOff,
        const float* __restrict__ Whh,
        const float* __restrict__ bih, const float* __restrict__ bhh,
        const int* __restrict__ x, int t, int which, int par)
{
    __shared__ __align__(16) float As[2][32][36];   // [k][row]
    __shared__ __align__(16) float Bs[2][32][68];   // [k][batch]
    __shared__ int s_last;

    int bx = blockIdx.x;
    int split = bx & 3;
    int grp   = bx >> 2;

    const float *zA, *zB;
    float *hout, *cst;
    if (which == 0) { zA = g_ctx;         zB = g_h1[par]; hout = g_h1[par ^ 1]; cst = g_c1; }
    else            { zA = g_h1[par ^ 1]; zB = g_h2[par]; hout = g_h2[par ^ 1]; cst = g_c2; }

    const float* z = (split < 2) ? zA : zB;
    int koffB = (split & 1) * 256;
    const float* Aw; int pitch, cb;
    if (split < 2) { Aw = Wih; pitch = pIh; cb = colOff + split * 256; }
    else           { Aw = Whh; pitch = 512; cb = (split - 2) * 256; }

    int tid  = threadIdx.x;
    int ka   = tid & 31, rseg = tid >> 5;   // A loader
    int bb   = tid >> 1, kseg = tid & 1;    // B loader
    int tr   = tid >> 4, tc   = tid & 15;   // compute tile

    float acc[4][4];
#pragma unroll
    for (int i = 0; i < 4; ++i)
#pragma unroll
        for (int j = 0; j < 4; ++j) acc[i][j] = 0.f;

    // chunk loader (32 k per chunk)
    auto load_chunk = [&](int c, int st) {
        int kb = c * 32;
#pragma unroll
        for (int j = 0; j < 8; ++j) {
            int r = rseg * 8 + j;
            int grow = (r >> 3) * 512 + grp * 8 + (r & 7);
            cp4(&As[st][ka][r], Aw + (size_t)grow * pitch + cb + kb + ka);
        }
#pragma unroll
        for (int j = 0; j < 16; ++j) {
            int k = kseg * 16 + j;
            cp4(&Bs[st][k][bb], z + bb * 512 + koffB + kb + k);
        }
        asm volatile("cp.async.commit_group;\n");
    };

    load_chunk(0, 0);
    for (int c = 0; c < 8; ++c) {
        int st = c & 1;
        if (c < 7) {
            load_chunk(c + 1, st ^ 1);
            asm volatile("cp.async.wait_group 1;\n");
        } else {
            asm volatile("cp.async.wait_group 0;\n");
        }
        __syncthreads();
#pragma unroll
        for (int kk = 0; kk < 32; ++kk) {
            float4 av = *(const float4*)&As[st][kk][tr * 4];
            float4 bv = *(const float4*)&Bs[st][kk][tc * 4];
            acc[0][0] = fmaf(av.x, bv.x, acc[0][0]);
            acc[0][1] = fmaf(av.x, bv.y, acc[0][1]);
            acc[0][2] = fmaf(av.x, bv.z, acc[0][2]);
            acc[0][3] = fmaf(av.x, bv.w, acc[0][3]);
            acc[1][0] = fmaf(av.y, bv.x, acc[1][0]);
            acc[1][1] = fmaf(av.y, bv.y, acc[1][1]);
            acc[1][2] = fmaf(av.y, bv.z, acc[1][2]);
            acc[1][3] = fmaf(av.y, bv.w, acc[1][3]);
            acc[2][0] = fmaf(av.z, bv.x, acc[2][0]);
            acc[2][1] = fmaf(av.z, bv.y, acc[2][1]);
            acc[2][2] = fmaf(av.z, bv.z, acc[2][2]);
            acc[2][3] = fmaf(av.z, bv.w, acc[2][3]);
            acc[3][0] = fmaf(av.w, bv.x, acc[3][0]);
            acc[3][1] = fmaf(av.w, bv.y, acc[3][1]);
            acc[3][2] = fmaf(av.w, bv.z, acc[3][2]);
            acc[3][3] = fmaf(av.w, bv.w, acc[3][3]);
        }
        __syncthreads();
    }

    // write partials
#pragma unroll
    for (int i = 0; i < 4; ++i) {
        int r = tr * 4 + i;
        int grow = (r >> 3) * 512 + grp * 8 + (r & 7);
#pragma unroll
        for (int j = 0; j < 4; ++j)
            g_part[(split * 2048 + grow) * B + tc * 4 + j] = acc[i][j];
    }
    __threadfence();
    __syncthreads();
    if (tid == 0)
        s_last = (atomicAdd(&g_cntL[which * 64 + grp], 1) == 3);
    __syncthreads();
    if (!s_last) return;

    // last-arriving K-split block does the gate epilogue for this unit group
    __threadfence();
#pragma unroll
    for (int q = 0; q < 4; ++q) {
        int idx = tid + q * 128;
        int u = idx >> 6, b = idx & 63;
        int unit = grp * 8 + u;
        float pre[4];
#pragma unroll
        for (int g = 0; g < 4; ++g) {
            int grow = g * 512 + unit;
            float s = bih[grow] + bhh[grow];
#pragma unroll
            for (int sp = 0; sp < 4; ++sp)
                s += g_part[(sp * 2048 + grow) * B + b];
            pre[g] = s;
        }
        if (which == 0) {
            int cls = x[b * NSTEP + t];
#pragma unroll
            for (int g = 0; g < 4; ++g)
                pre[g] += Wih[(size_t)(g * 512 + unit) * pIh + cls];
        }
        float co = cst[b * S + unit];
        float cn = sigf(pre[1]) * co + sigf(pre[0]) * tanhf(pre[2]);
        float hn = sigf(pre[3]) * tanhf(cn);
        cst[b * S + unit]  = cn;
        hout[b * S + unit] = hn;
    }
    __syncthreads();
    if (tid == 0) g_cntL[which * 64 + grp] = 0;
}

// ---------------- attention scores: phi, e, softmax -> alpha (one block/batch) ---
__global__ void k_attnA(const float* __restrict__ Wphi, const float* __restrict__ bphi,
                        int par)
{
    __shared__ __align__(16) float h2s[S];
    __shared__ __align__(16) float phis[ATT];
    __shared__ __align__(16) float es[T];
    __shared__ float red[8];

    int b    = blockIdx.x;
    int tid  = threadIdx.x;
    int wid  = tid >> 5;
    int lane = tid & 31;
    const float* h2 = g_h2[par ^ 1];

    for (int d = tid; d < S; d += 256) h2s[d] = h2[b * S + d];
    __syncthreads();

    for (int a = wid * 16; a < wid * 16 + 16; ++a) {
        const float* wr = Wphi + a * S;
        float s = 0.f;
#pragma unroll 4
        for (int i = lane; i < S; i += 32) s = fmaf(wr[i], h2s[i], s);
#pragma unroll
        for (int o = 16; o > 0; o >>= 1) s += __shfl_xor_sync(0xffffffffu, s, o);
        if (lane == 0) phis[a] = s + bphi[a];
    }
    __syncthreads();

    float ph0, ph1, ph2, ph3;
    {
        float4 p4 = *(const float4*)&phis[lane * 4];
        ph0 = p4.x; ph1 = p4.y; ph2 = p4.z; ph3 = p4.w;
    }
    const float* psib = g_psi + (size_t)b * T * ATT;
    for (int tt = wid * 64; tt < wid * 64 + 64; ++tt) {
        float4 v = *(const float4*)&psib[tt * ATT + lane * 4];
        float s = ph0 * v.x + ph1 * v.y + ph2 * v.z + ph3 * v.w;
#pragma unroll
        for (int o = 16; o > 0; o >>= 1) s += __shfl_xor_sync(0xffffffffu, s, o);
        if (lane == 0) es[tt] = s;
    }
    __syncthreads();

    float m = fmaxf(es[tid], es[tid + 256]);
#pragma unroll
    for (int o = 16; o > 0; o >>= 1) m = fmaxf(m, __shfl_xor_sync(0xffffffffu, m, o));
    if (lane == 0) red[wid] = m;
    __syncthreads();
    if (tid == 0) {
        float mm = red[0];
        for (int i = 1; i < 8; ++i) mm = fmaxf(mm, red[i]);
        red[0] = mm;
    }
    __syncthreads();
    m = red[0];
    float e0 = expf(es[tid] - m), e1 = expf(es[tid + 256] - m);
    float ssum = e0 + e1;
#pragma unroll
    for (int o = 16; o > 0; o >>= 1) ssum += __shfl_xor_sync(0xffffffffu, ssum, o);
    __syncthreads();
    if (lane == 0) red[wid] = ssum;
    __syncthreads();
    if (tid == 0) {
        float s = 0.f;
        for (int i = 0; i < 8; ++i) s += red[i];
        red[0] = 1.f / s;
    }
    __syncthreads();
    float inv = red[0];
    g_alpha[b * T + tid]       = e0 * inv;
    g_alpha[b * T + tid + 256] = e1 * inv;
}

// ---------------- context reduction (parallel over dims) + fused projection -----
// grid 256 = 64 batches x 4 dim-chunks of 128. block 128 threads.
__global__ void __launch_bounds__(128) k_ctxproj(
        const float* __restrict__ h,
        const float* __restrict__ Wcd, const float* __restrict__ bcd,
        float* __restrict__ out, int t, int par)
{
    __shared__ __align__(16) float al[T];
    __shared__ __align__(16) float sred[4][128];
    __shared__ __align__(16) float vec[S + H2D];
    __shared__ int s_last;

    int bx   = blockIdx.x;
    int b    = bx >> 2;
    int ch   = bx & 3;
    int tid  = threadIdx.x;
    int wid  = tid >> 5;
    int lane = tid & 31;

    *(float4*)&al[tid * 4] = ((const float4*)(g_alpha + b * T))[tid];
    __syncthreads();

    const float* hb = h + (size_t)b * T * H2D;
    int d0 = ch * 128 + lane * 4;
    float ax = 0.f, ay = 0.f, az = 0.f, aw = 0.f;
#pragma unroll 8
    for (int tt = wid; tt < T; tt += 4) {
        float a = al[tt];
        float4 hv = *(const float4*)&hb[tt * H2D + d0];
        ax = fmaf(a, hv.x, ax);
        ay = fmaf(a, hv.y, ay);
        az = fmaf(a, hv.z, az);
        aw = fmaf(a, hv.w, aw);
    }
    sred[wid][lane * 4 + 0] = ax;
    sred[wid][lane * 4 + 1] = ay;
    sred[wid][lane * 4 + 2] = az;
    sred[wid][lane * 4 + 3] = aw;
    __syncthreads();
    {
        float v = sred[0][tid] + sred[1][tid] + sred[2][tid] + sred[3][tid];
        g_ctx[b * H2D + ch * 128 + tid] = v;
    }
    __threadfence();
    __syncthreads();
    if (tid == 0)
        s_last = (atomicAdd(&g_cntC[b], 1) == 3);
    __syncthreads();
    if (!s_last) return;

    // last chunk-block of this batch: output projection p = Wcd @ [h2; ctx] + bcd
    __threadfence();
    const float* h2 = g_h2[par ^ 1];
    for (int i = tid; i < S; i += 128) {
        vec[i]     = h2[b * S + i];
        vec[S + i] = g_ctx[b * H2D + i];
    }
    __syncthreads();

#pragma unroll
    for (int ci = 0; ci < 16; ++ci) {
        int c = wid * 16 + ci;
        const float* wr = Wcd + c * (S + H2D);
        float s = 0.f;
#pragma unroll
        for (int i = lane * 4; i < S + H2D; i += 128) {
            float4 w4 = *(const float4*)&wr[i];
            float4 v4 = *(const float4*)&vec[i];
            s = fmaf(w4.x, v4.x, s);
            s = fmaf(w4.y, v4.y, s);
            s = fmaf(w4.z, v4.z, s);
            s = fmaf(w4.w, v4.w, s);
        }
#pragma unroll
        for (int o = 16; o > 0; o >>= 1) s += __shfl_xor_sync(0xffffffffu, s, o);
        if (lane == 0) out[((size_t)b * NSTEP + t) * NCLS + c] = s + bcd[c];
    }
    __syncthreads();
    if (tid == 0) g_cntC[b] = 0;
}

// ---------------- launcher ----------------
extern "C" void kernel_launch(void* const* d_in, const int* in_sizes, int n_in,
                              void* d_out, int out_size)
{
    const int*   x    = (const int*)d_in[0];
    const float* h    = (const float*)d_in[1];
    const float* Wih0 = (const float*)d_in[2];
    const float* Whh0 = (const float*)d_in[3];
    const float* bih0 = (const float*)d_in[4];
    const float* bhh0 = (const float*)d_in[5];
    const float* Wih1 = (const float*)d_in[6];
    const float* Whh1 = (const float*)d_in[7];
    const float* bih1 = (const float*)d_in[8];
    const float* bhh1 = (const float*)d_in[9];
    const float* Wphi = (const float*)d_in[10];
    const float* bphi = (const float*)d_in[11];
    const float* Wpsi = (const float*)d_in[12];
    const float* bpsi = (const float*)d_in[13];
    const float* Wcd  = (const float*)d_in[14];
    const float* bcd  = (const float*)d_in[15];
    float* out = (float*)d_out;

    k_init<<<B, 512>>>(h);
    k_psi<<<dim3(T / 32, B), 256>>>(h, Wpsi, bpsi);

    int par = 0;
    for (int t = 0; t < NSTEP; ++t) {
        k_lstm<<<256, 128>>>(Wih0, 576, 64, Whh0, bih0, bhh0, x, t, 0, par);
        k_lstm<<<256, 128>>>(Wih1, 512, 0,  Whh1, bih1, bhh1, x, t, 1, par);
        k_attnA<<<B, 256>>>(Wphi, bphi, par);
        k_ctxproj<<<256, 128>>>(h, Wcd, bcd, out, t, par);
        par ^= 1;
    }
}

// round 4
// speedup vs baseline: 3.0339x; 1.8538x over previous
#include <cuda_runtime.h>
#include <math.h>

#define B     64
#define T     512
#define NSTEP 128
#define S     512
#define H2D   512
#define ATT   128
#define NCLS  64
#define GRID  148
#define NTH   512

// ---------------- scratch (static device globals; no allocation) ----------------
__device__ float g_psi[B * T * ATT];        // psi_h = h @ Wpsi.T + bpsi (16.8 MB)
__device__ float g_part[8 * 2048 * B];      // K-split partial gate sums (4 MB)
__device__ float g_h1[2][B * S];
__device__ float g_h2[2][B * S];
__device__ float g_c1[B * S];
__device__ float g_c2[B * S];
__device__ float g_ctx[B * H2D];
__device__ unsigned g_cnt1[8];              // zero-init; self-resetting
__device__ unsigned g_cnt2;
__device__ volatile unsigned g_epoch;       // monotone across launches

__device__ __forceinline__ float tanh_fast(float v)
{
    float r;
    asm("tanh.approx.f32 %0, %1;" : "=f"(r) : "f"(v));
    return r;
}
__device__ __forceinline__ float sigf(float v) { return 0.5f * tanh_fast(0.5f * v) + 0.5f; }

__device__ __forceinline__ void cp4(void* s, const void* g)
{
    unsigned sa = (unsigned)__cvta_generic_to_shared(s);
    asm volatile("cp.async.ca.shared.global [%0], [%1], 4;\n" :: "r"(sa), "l"(g));
}

// -------- two-level grid barrier (all 148 CTAs co-resident by construction) -----
__device__ __forceinline__ void gbar(unsigned& phase, int cta)
{
    __syncthreads();
    if (threadIdx.x == 0) {
        ++phase;
        __threadfence();
        int grp = cta & 7;
        unsigned gsz = 18u + (grp < 4 ? 1u : 0u);   // 148 = 4*19 + 4*18
        if (atomicAdd(&g_cnt1[grp], 1u) == gsz - 1u) {
            g_cnt1[grp] = 0u;
            __threadfence();
            if (atomicAdd(&g_cnt2, 1u) == 7u) {
                g_cnt2 = 0u;
                __threadfence();
                g_epoch = phase;
            } else {
                while (g_epoch != phase) {}
            }
        } else {
            while (g_epoch != phase) {}
        }
        __threadfence();
    }
    __syncthreads();
}

// ---------------- smem overlay ----------------
struct SmG { float A[2][16][132]; float Bm[2][16][68]; };           // ~25.9 KB
struct SmA { float vec[1024]; float phi[128]; float al[512]; float red[32]; };
union SmU { SmG g; SmA a; };

// -------- LSTM partial GEMM: 128 gate rows x 64 batches x K=128, tile 4x4 -------
__device__ __forceinline__ void lstm_gemm(SmG* s, int tid,
        const float* __restrict__ Aw, int pitch, int cb,
        const float* __restrict__ z, int koffB, int row0, int sp)
{
    int ka = tid & 15;          // k within chunk
    int rr = tid >> 4;          // 0..31
    int tr = tid >> 4;          // 4 rows each
    int tc = tid & 15;          // 4 batches each

    float acc[4][4];
#pragma unroll
    for (int i = 0; i < 4; ++i)
#pragma unroll
        for (int j = 0; j < 4; ++j) acc[i][j] = 0.f;

    auto load = [&](int cbase, int st) {
        const float* a0 = Aw + (size_t)(row0 + rr) * pitch + cb + cbase + ka;
        cp4(&s->A[st][ka][rr],      a0);
        cp4(&s->A[st][ka][rr + 32], a0 + (size_t)32 * pitch);
        cp4(&s->A[st][ka][rr + 64], a0 + (size_t)64 * pitch);
        cp4(&s->A[st][ka][rr + 96], a0 + (size_t)96 * pitch);
        const float* b0 = z + rr * S + koffB + cbase + ka;
        cp4(&s->Bm[st][ka][rr],      b0);
        cp4(&s->Bm[st][ka][rr + 32], b0 + 32 * S);
        asm volatile("cp.async.commit_group;\n");
    };

    load(0, 0);
    for (int c = 0; c < 8; ++c) {
        int st = c & 1;
        if (c < 7) {
            load((c + 1) * 16, st ^ 1);
            asm volatile("cp.async.wait_group 1;\n");
        } else {
            asm volatile("cp.async.wait_group 0;\n");
        }
        __syncthreads();
#pragma unroll
        for (int kk = 0; kk < 16; ++kk) {
            float4 av = *(const float4*)&s->A[st][kk][tr * 4];
            float4 bv = *(const float4*)&s->Bm[st][kk][tc * 4];
            acc[0][0] = fmaf(av.x, bv.x, acc[0][0]);
            acc[0][1] = fmaf(av.x, bv.y, acc[0][1]);
            acc[0][2] = fmaf(av.x, bv.z, acc[0][2]);
            acc[0][3] = fmaf(av.x, bv.w, acc[0][3]);
            acc[1][0] = fmaf(av.y, bv.x, acc[1][0]);
            acc[1][1] = fmaf(av.y, bv.y, acc[1][1]);
            acc[1][2] = fmaf(av.y, bv.z, acc[1][2]);
            acc[1][3] = fmaf(av.y, bv.w, acc[1][3]);
            acc[2][0] = fmaf(av.z, bv.x, acc[2][0]);
            acc[2][1] = fmaf(av.z, bv.y, acc[2][1]);
            acc[2][2] = fmaf(av.z, bv.z, acc[2][2]);
            acc[2][3] = fmaf(av.z, bv.w, acc[2][3]);
            acc[3][0] = fmaf(av.w, bv.x, acc[3][0]);
            acc[3][1] = fmaf(av.w, bv.y, acc[3][1]);
            acc[3][2] = fmaf(av.w, bv.z, acc[3][2]);
            acc[3][3] = fmaf(av.w, bv.w, acc[3][3]);
        }
        __syncthreads();
    }
#pragma unroll
    for (int i = 0; i < 4; ++i) {
        int row = row0 + tr * 4 + i;
        float4 v = make_float4(acc[i][0], acc[i][1], acc[i][2], acc[i][3]);
        *(float4*)&g_part[(size_t)((sp << 11) + row) * 64 + tc * 4] = v;
    }
}

// -------- LSTM epilogue: sum 8 splits + bias (+ one-hot col), gates, state ------
__device__ __forceinline__ void lstm_epi(int cta, int tid,
        const float* __restrict__ Wih, int pIh,
        const float* __restrict__ bih, const float* __restrict__ bhh,
        float* __restrict__ cst, float* __restrict__ hout,
        const int* __restrict__ x, int t, int onehot)
{
    if (cta >= 64) return;
    int id = cta * NTH + tid;
    int u = id >> 6, b = id & 63;
    float pre[4];
#pragma unroll
    for (int gi = 0; gi < 4; ++gi) {
        int row = gi * 512 + u;
        float sum = bih[row] + bhh[row];
#pragma unroll
        for (int sp = 0; sp < 8; ++sp)
            sum += g_part[(size_t)((sp << 11) + row) * 64 + b];
        pre[gi] = sum;
    }
    if (onehot) {
        int cls = x[b * NSTEP + t];
#pragma unroll
        for (int gi = 0; gi < 4; ++gi)
            pre[gi] += Wih[(size_t)(gi * 512 + u) * pIh + cls];
    }
    float co = cst[b * S + u];
    float cn = sigf(pre[1]) * co + sigf(pre[0]) * tanh_fast(pre[2]);
    float hn = sigf(pre[3]) * tanh_fast(cn);
    cst[b * S + u]  = cn;
    hout[b * S + u] = hn;
}

// -------- fused attention + output projection, one CTA per batch ----------------
__device__ __forceinline__ void attn_phase(SmA* a, int cta, int tid,
        const float* __restrict__ h,
        const float* __restrict__ Wphi, const float* __restrict__ bphi,
        const float* __restrict__ Wcd,  const float* __restrict__ bcd,
        const float* __restrict__ h2v, float* __restrict__ out, int t)
{
    if (cta >= B) return;
    int b    = cta;
    int wid  = tid >> 5;
    int lane = tid & 31;

    a->vec[tid] = h2v[b * S + tid];
    __syncthreads();

    // phi = Wphi @ h2 + bphi (16 warps x 8 rows)
#pragma unroll
    for (int i = 0; i < 8; ++i) {
        int aa = wid * 8 + i;
        const float* wr = Wphi + aa * S;
        float sum = 0.f;
#pragma unroll
        for (int idx = lane * 4; idx < S; idx += 128) {
            float4 w4 = *(const float4*)&wr[idx];
            float4 v4 = *(const float4*)&a->vec[idx];
            sum = fmaf(w4.x, v4.x, sum);
            sum = fmaf(w4.y, v4.y, sum);
            sum = fmaf(w4.z, v4.z, sum);
            sum = fmaf(w4.w, v4.w, sum);
        }
#pragma unroll
        for (int o = 16; o > 0; o >>= 1) sum += __shfl_xor_sync(0xffffffffu, sum, o);
        if (lane == 0) a->phi[aa] = sum + bphi[aa];
    }
    __syncthreads();

    // e[tt] = phi . psi[b,tt,:] (16 warps x 32 rows)
    float4 p4 = *(const float4*)&a->phi[lane * 4];
    const float* psib = g_psi + (size_t)b * T * ATT;
    for (int tt = wid * 32; tt < wid * 32 + 32; ++tt) {
        float4 v = *(const float4*)&psib[tt * ATT + lane * 4];
        float sum = p4.x * v.x + p4.y * v.y + p4.z * v.z + p4.w * v.w;
#pragma unroll
        for (int o = 16; o > 0; o >>= 1) sum += __shfl_xor_sync(0xffffffffu, sum, o);
        if (lane == 0) a->al[tt] = sum;
    }
    __syncthreads();

    // softmax over 512 (one value per thread)
    float e = a->al[tid];
    float m = e;
#pragma unroll
    for (int o = 16; o > 0; o >>= 1) m = fmaxf(m, __shfl_xor_sync(0xffffffffu, m, o));
    if (lane == 0) a->red[wid] = m;
    __syncthreads();
    if (tid == 0) {
        float mm = a->red[0];
        for (int i = 1; i < 16; ++i) mm = fmaxf(mm, a->red[i]);
        a->red[16] = mm;
    }
    __syncthreads();
    m = a->red[16];
    float ex = __expf(e - m);
    a->al[tid] = ex;
    float ssum = ex;
#pragma unroll
    for (int o = 16; o > 0; o >>= 1) ssum += __shfl_xor_sync(0xffffffffu, ssum, o);
    if (lane == 0) a->red[wid] = ssum;
    __syncthreads();
    if (tid == 0) {
        float s = 0.f;
        for (int i = 0; i < 16; ++i) s += a->red[i];
        a->red[17] = 1.f / s;
    }
    __syncthreads();
    float inv = a->red[17];

    // ctx[d] = inv * sum_tt ex[tt] * h[b,tt,d] (thread owns one d)
    {
        const float* hb = h + (size_t)b * T * H2D;
        float acc = 0.f;
#pragma unroll 16
        for (int tt = 0; tt < T; ++tt)
            acc = fmaf(a->al[tt], hb[tt * H2D + tid], acc);
        float cv = acc * inv;
        a->vec[S + tid] = cv;
        g_ctx[b * H2D + tid] = cv;
    }
    __syncthreads();

    // out = Wcd @ [h2; ctx] + bcd (16 warps x 4 classes)
#pragma unroll
    for (int i = 0; i < 4; ++i) {
        int c = wid * 4 + i;
        const float* wr = Wcd + c * (S + H2D);
        float sum = 0.f;
#pragma unroll
        for (int idx = lane * 4; idx < S + H2D; idx += 128) {
            float4 w4 = *(const float4*)&wr[idx];
            float4 v4 = *(const float4*)&a->vec[idx];
            sum = fmaf(w4.x, v4.x, sum);
            sum = fmaf(w4.y, v4.y, sum);
            sum = fmaf(w4.z, v4.z, sum);
            sum = fmaf(w4.w, v4.w, sum);
        }
#pragma unroll
        for (int o = 16; o > 0; o >>= 1) sum += __shfl_xor_sync(0xffffffffu, sum, o);
        if (lane == 0) out[((size_t)b * NSTEP + t) * NCLS + c] = sum + bcd[c];
    }
    __syncthreads();
}

// ---------------- psi_h precompute: GEMM per batch, tile 32t x 128a ----------------
__global__ void k_psi(const float* __restrict__ h,
                      const float* __restrict__ Wpsi,
                      const float* __restrict__ bpsi)
{
    __shared__ __align__(16) float hs[32][36];
    __shared__ __align__(16) float ws[128][36];
    int b   = blockIdx.y;
    int t0  = blockIdx.x * 32;
    int tid = threadIdx.x;
    int tg  = tid & 7;
    int ag  = tid >> 3;

    float acc[16];
#pragma unroll
    for (int i = 0; i < 16; ++i) acc[i] = 0.f;

    for (int dc = 0; dc < H2D; dc += 32) {
#pragma unroll
        for (int i = 0; i < 4; ++i) {
            int lin = tid + i * 256;
            int r = lin >> 5, c = lin & 31;
            hs[r][c] = h[((size_t)b * T + t0 + r) * H2D + dc + c];
        }
#pragma unroll
        for (int i = 0; i < 16; ++i) {
            int lin = tid + i * 256;
            int r = lin >> 5, c = lin & 31;
            ws[r][c] = Wpsi[r * H2D + dc + c];
        }
        __syncthreads();
#pragma unroll
        for (int k = 0; k < 32; k += 4) {
            float4 hv[4], wv[4];
#pragma unroll
            for (int j = 0; j < 4; ++j) hv[j] = *(const float4*)&hs[tg * 4 + j][k];
#pragma unroll
            for (int j = 0; j < 4; ++j) wv[j] = *(const float4*)&ws[ag * 4 + j][k];
#pragma unroll
            for (int i = 0; i < 4; ++i)
#pragma unroll
                for (int j = 0; j < 4; ++j) {
                    acc[i * 4 + j] = fmaf(hv[i].x, wv[j].x, acc[i * 4 + j]);
                    acc[i * 4 + j] = fmaf(hv[i].y, wv[j].y, acc[i * 4 + j]);
                    acc[i * 4 + j] = fmaf(hv[i].z, wv[j].z, acc[i * 4 + j]);
                    acc[i * 4 + j] = fmaf(hv[i].w, wv[j].w, acc[i * 4 + j]);
                }
        }
        __syncthreads();
    }
#pragma unroll
    for (int i = 0; i < 4; ++i)
#pragma unroll
        for (int j = 0; j < 4; ++j) {
            int tt = t0 + tg * 4 + i;
            int a  = ag * 4 + j;
            g_psi[((size_t)b * T + tt) * ATT + a] = acc[i * 4 + j] + bpsi[a];
        }
}

// ---------------- the persistent mega kernel ----------------
__global__ void __launch_bounds__(NTH, 1) k_mega(
        const int* __restrict__ x, const float* __restrict__ h,
        const float* __restrict__ Wih0, const float* __restrict__ Whh0,
        const float* __restrict__ bih0, const float* __restrict__ bhh0,
        const float* __restrict__ Wih1, const float* __restrict__ Whh1,
        const float* __restrict__ bih1, const float* __restrict__ bhh1,
        const float* __restrict__ Wphi, const float* __restrict__ bphi,
        const float* __restrict__ Wcd,  const float* __restrict__ bcd,
        float* __restrict__ out)
{
    __shared__ SmU sm;

    int cta = blockIdx.x;
    int tid = threadIdx.x;
    unsigned phase = 0;
    if (tid == 0) phase = g_epoch;   // resume epoch (graph replays keep counting)

    // init: states zero, ctx = h[:,0,:]
    if (cta < B) {
        int b = cta;
        g_ctx[b * S + tid]   = h[(size_t)b * T * H2D + tid];
        g_h1[0][b * S + tid] = 0.f;
        g_h2[0][b * S + tid] = 0.f;
        g_c1[b * S + tid]    = 0.f;
        g_c2[b * S + tid]    = 0.f;
    }
    gbar(phase, cta);

    for (int t = 0; t < NSTEP; ++t) {
        int par = t & 1;

        // Phase A: LSTM0 partial GEMMs (128 WUs)
        if (cta < 128) {
            int rg = cta >> 3, sp = cta & 7;
            const float* Aw; int pitch, cb; const float* z;
            if (sp < 4) { Aw = Wih0; pitch = 576; cb = 64 + sp * 128; z = g_ctx; }
            else        { Aw = Whh0; pitch = 512; cb = (sp - 4) * 128; z = g_h1[par]; }
            lstm_gemm(&sm.g, tid, Aw, pitch, cb, z, (sp & 3) * 128, rg * 128, sp);
        }
        gbar(phase, cta);

        // Phase B: LSTM0 epilogue
        lstm_epi(cta, tid, Wih0, 576, bih0, bhh0, g_c1, g_h1[par ^ 1], x, t, 1);
        gbar(phase, cta);

        // Phase C: LSTM1 partial GEMMs
        if (cta < 128) {
            int rg = cta >> 3, sp = cta & 7;
            const float* Aw; int cb; const float* z;
            if (sp < 4) { Aw = Wih1; cb = sp * 128;       z = g_h1[par ^ 1]; }
            else        { Aw = Whh1; cb = (sp - 4) * 128; z = g_h2[par]; }
            lstm_gemm(&sm.g, tid, Aw, 512, cb, z, (sp & 3) * 128, rg * 128, sp);
        }
        gbar(phase, cta);

        // Phase D: LSTM1 epilogue
        lstm_epi(cta, tid, Wih1, 512, bih1, bhh1, g_c2, g_h2[par ^ 1], x, t, 0);
        gbar(phase, cta);

        // Phase E: attention + projection
        attn_phase(&sm.a, cta, tid, h, Wphi, bphi, Wcd, bcd, g_h2[par ^ 1], out, t);
        gbar(phase, cta);
    }
}

// ---------------- launcher ----------------
extern "C" void kernel_launch(void* const* d_in, const int* in_sizes, int n_in,
                              void* d_out, int out_size)
{
    const int*   x    = (const int*)d_in[0];
    const float* h    = (const float*)d_in[1];
    const float* Wih0 = (const float*)d_in[2];
    const float* Whh0 = (const float*)d_in[3];
    const float* bih0 = (const float*)d_in[4];
    const float* bhh0 = (const float*)d_in[5];
    const float* Wih1 = (const float*)d_in[6];
    const float* Whh1 = (const float*)d_in[7];
    const float* bih1 = (const float*)d_in[8];
    const float* bhh1 = (const float*)d_in[9];
    const float* Wphi = (const float*)d_in[10];
    const float* bphi = (const float*)d_in[11];
    const float* Wpsi = (const float*)d_in[12];
    const float* bpsi = (const float*)d_in[13];
    const float* Wcd  = (const float*)d_in[14];
    const float* bcd  = (const float*)d_in[15];
    float* out = (float*)d_out;

    k_psi<<<dim3(T / 32, B), 256>>>(h, Wpsi, bpsi);
    k_mega<<<GRID, NTH>>>(x, h, Wih0, Whh0, bih0, bhh0,
                          Wih1, Whh1, bih1, bhh1,
                          Wphi, bphi, Wcd, bcd, out);
}